// round 14
// baseline (speedup 1.0000x reference)
#include <cuda_runtime.h>
#include <stdint.h>

// ---------------------------------------------------------------------------
// Scratch
// ---------------------------------------------------------------------------
__device__ float g_bev_feat[8 * 128 * 1024];   // (bt, c, n) tf32-rounded
__device__ float g_kv[8 * 192 * 1024];         // (bt, c, n) tf32-rounded
__device__ float g_Q[8 * 4 * 1024 * 32];       // (bt,h,n,d) tf32, scaled
__device__ float g_Kp[8 * 4 * 16 * 2048];      // packed B-fragments per 64-key tile
__device__ float g_Vp[8 * 4 * 16 * 2048];      // packed (incl. sigma permutation)
__device__ float g_attn[8 * 1024 * 128];       // (bt, n, c)
__device__ float g_fused[8 * 128 * 1024];      // (bt, c, n)
__device__ float g_Wp[81920];                  // fragment-packed tf32 wq|wk|wv|wo

// ---------------------------------------------------------------------------
// Helpers
// ---------------------------------------------------------------------------
__device__ __forceinline__ float f2tf(float x) {
    uint32_t u;
    asm("cvt.rna.tf32.f32 %0,%1;" : "=r"(u) : "f"(x));
    return __uint_as_float(u);
}
__device__ __forceinline__ float ex2f(float x) {
    float y;
    asm("ex2.approx.f32 %0,%1;" : "=f"(y) : "f"(x));
    return y;
}
__device__ __forceinline__ void mma8(float* c, float a0, float a1, float a2,
                                     float a3, float b0, float b1) {
    asm("mma.sync.aligned.m16n8k8.row.col.f32.tf32.tf32.f32 "
        "{%0,%1,%2,%3},{%4,%5,%6,%7},{%8,%9},{%0,%1,%2,%3};"
        : "+f"(c[0]), "+f"(c[1]), "+f"(c[2]), "+f"(c[3])
        : "r"(__float_as_uint(a0)), "r"(__float_as_uint(a1)),
          "r"(__float_as_uint(a2)), "r"(__float_as_uint(a3)),
          "r"(__float_as_uint(b0)), "r"(__float_as_uint(b1)));
}
#define CP16(dst, src)                                                        \
    {                                                                         \
        uint32_t _s = (uint32_t)__cvta_generic_to_shared(dst);                \
        asm volatile("cp.async.cg.shared.global [%0], [%1], 16;" ::"r"(_s),   \
                     "l"(src));                                               \
    }
#define CP_COMMIT() asm volatile("cp.async.commit_group;")
#define CP_WAIT0() asm volatile("cp.async.wait_group 0;")
#define CP_WAIT1() asm volatile("cp.async.wait_group 1;")

// ---------------------------------------------------------------------------
// Conv 3x3 SAME implicit GEMM, OCW oc x 256px (8 rows), dual-path.
// (unchanged from R13 — best known)
// ---------------------------------------------------------------------------
template <int OCW>
__global__ __launch_bounds__(256) void conv_dual_kernel(
    const float* __restrict__ in0, const float* __restrict__ w0,
    const float* __restrict__ bias0, float* __restrict__ out0, int ld0, int cin0, int ctot0,
    const float* __restrict__ in1, const float* __restrict__ w1,
    const float* __restrict__ bias1, float* __restrict__ out1, int ld1, int cin1, int ctot1,
    const float* __restrict__ ego, int xsplit,
    const float* __restrict__ front, int rsplit,
    const float* __restrict__ wq, const float* __restrict__ wk,
    const float* __restrict__ wv, const float* __restrict__ wo,
    int psplit, int rnd)
{
    constexpr int NOM = OCW / 16;
    constexpr int NSLOT = OCW / 32;

    if ((int)blockIdx.x >= psplit) {
        if (blockIdx.z != 0) return;
        int t = ((blockIdx.x - psplit) * 4 + blockIdx.y) * 256 + threadIdx.x;
        if (t >= 20480) return;
        int which, rem, Cdim, base;
        if (t < 4096)       { which = 0; rem = t;         Cdim = 128; base = 0; }
        else if (t < 10240) { which = 1; rem = t - 4096;  Cdim = 192; base = 16384; }
        else if (t < 16384) { which = 2; rem = t - 10240; Cdim = 192; base = 40960; }
        else                { which = 3; rem = t - 16384; Cdim = 128; base = 65536; }
        const float* W = which == 0 ? wq : (which == 1 ? wk : (which == 2 ? wv : wo));
        int NCH = Cdim >> 3;
        int lane = rem & 31;
        int om = (rem >> 5) & 3;
        int sg = (rem >> 7) % NCH;
        int ogrp = (rem >> 7) / NCH;
        int g2 = lane >> 2, t4 = lane & 3;
        int o = ogrp * 64 + om * 16 + g2;
        int k = sg * 8 + t4;
        float4 v;
        v.x = f2tf(W[(size_t)o * Cdim + k]);
        v.y = f2tf(W[(size_t)(o + 8) * Cdim + k]);
        v.z = f2tf(W[(size_t)o * Cdim + k + 4]);
        v.w = f2tf(W[(size_t)(o + 8) * Cdim + k + 4]);
        *(float4*)&g_Wp[base + rem * 4] = v;
        return;
    }

    if ((int)blockIdx.x >= rsplit) {
        int idx = ((blockIdx.x - rsplit) * 4 + blockIdx.y) * 256 + threadIdx.x;
        int bt = blockIdx.z;
        int c = idx >> 8, p4 = (idx & 255) * 4;
        int y = p4 >> 5;
        const float* src = front + (bt * 64 + c) * 256;
        float sy = y * 0.5f - 0.25f;
        int y0 = __float2int_rd(sy);
        float fy = sy - (float)y0;
        int y0c = max(y0, 0), y1c = min(y0 + 1, 15);
        float o[4];
#pragma unroll
        for (int i = 0; i < 4; i++) {
            int x = (p4 & 31) + i;
            float sx = x * 0.5f - 0.25f;
            int x0 = __float2int_rd(sx);
            float fx = sx - (float)x0;
            int x0c = max(x0, 0), x1c = min(x0 + 1, 15);
            float a = src[y0c * 16 + x0c], b = src[y0c * 16 + x1c];
            float cc = src[y1c * 16 + x0c], d = src[y1c * 16 + x1c];
            float top = a + fx * (b - a), bot = cc + fx * (d - cc);
            o[i] = f2tf(top + fy * (bot - top));
        }
        float4 v = {o[0], o[1], o[2], o[3]};
        *(float4*)(g_kv + (size_t)(bt * 192 + 128 + c) * 1024 + p4) = v;
        return;
    }

    const int path = (int)blockIdx.x >= xsplit;
    const float* in = path ? in1 : in0;
    const float* w = path ? w1 : w0;
    const float* bias = path ? bias1 : bias0;
    float* out = path ? out1 : out0;
    const int ld_out = path ? ld1 : ld0;
    const int CIN = path ? cin1 : cin0;
    const int CTOT = path ? ctot1 : ctot0;
    const int NCH = CTOT >> 3;
    const int oc_base = (path ? blockIdx.x - xsplit : blockIdx.x) * OCW;
    const int y0 = blockIdx.y * 8;
    const int bt = blockIdx.z;
    const int tid = threadIdx.x;
    const int warp = tid >> 5, lane = tid & 31;
    const int g = lane >> 2, t4 = lane & 3;
    const int pw = warp;

    __shared__ float s_in[4 * 680];
    __shared__ float s_wf[NOM * 1152];

    int pack[11];
    unsigned vmask = 0, amask = 0;
#pragma unroll
    for (int s = 0; s < 11; s++) {
        int idx = tid + s * 256;
        pack[s] = 0;
        if (idx < 2720) {
            amask |= 1u << s;
            int icl = idx / 340, rem = idx - icl * 340;
            int rr = rem / 34, cc = rem - rr * 34;
            int Y = y0 - 1 + rr, X = cc - 1;
            int sdst = (icl & 3) * 680 + rem * 2 + (icl >> 2);
            int ssrc = 0;
            if ((unsigned)Y < 32u && (unsigned)X < 32u) {
                vmask |= 1u << s;
                ssrc = icl * 1024 + Y * 32 + X;
            }
            pack[s] = sdst | (ssrc << 12) | (icl << 25);
        }
    }
    int wocS[NSLOT], wiclS[NSLOT], wfbS[NSLOT];
#pragma unroll
    for (int sl = 0; sl < NSLOT; sl++) {
        int s = tid + sl * 256;
        int woc = s >> 3, wicl = s & 7;
        wocS[sl] = woc; wiclS[sl] = wicl;
        wfbS[sl] = (woc >> 4) * 1152 + ((woc & 7) * 4 + (wicl & 3)) * 4 +
                   ((woc >> 3) & 1) + 2 * (wicl >> 2);
    }

    float C[NOM][4][4];
#pragma unroll
    for (int om = 0; om < NOM; om++)
#pragma unroll
        for (int nt = 0; nt < 4; nt++)
#pragma unroll
            for (int i = 0; i < 4; i++) C[om][nt][i] = 0.f;

    float pin[11], pwv[NSLOT][9];
    {
        const float* src = in + (size_t)bt * CIN * 1024;
#pragma unroll
        for (int s = 0; s < 11; s++)
            pin[s] = (vmask >> s & 1) ? __ldg(src + ((pack[s] >> 12) & 0x1FFF)) : 0.f;
#pragma unroll
        for (int sl = 0; sl < NSLOT; sl++) {
            const float* wp = w + ((size_t)(oc_base + wocS[sl]) * CTOT + wiclS[sl]) * 9;
#pragma unroll
            for (int j = 0; j < 9; j++) pwv[sl][j] = __ldg(wp + j);
        }
    }

    for (int ch = 0; ch < NCH; ch++) {
#pragma unroll
        for (int s = 0; s < 11; s++)
            if (amask >> s & 1) s_in[pack[s] & 0xFFF] = f2tf(pin[s]);
#pragma unroll
        for (int sl = 0; sl < NSLOT; sl++)
#pragma unroll
            for (int j = 0; j < 9; j++) s_wf[wfbS[sl] + j * 128] = f2tf(pwv[sl][j]);
        __syncthreads();

        if (ch + 1 < NCH) {
            int ic0 = (ch + 1) * 8;
            if (ic0 < CIN) {
                const float* src = in + (size_t)(bt * CIN + ic0) * 1024;
#pragma unroll
                for (int s = 0; s < 11; s++)
                    pin[s] = (vmask >> s & 1) ? __ldg(src + ((pack[s] >> 12) & 0x1FFF)) : 0.f;
            } else {
                const float* e = ego + bt * 16 + (ic0 - CIN);
#pragma unroll
                for (int s = 0; s < 11; s++)
                    pin[s] = (vmask >> s & 1) ? __ldg(e + ((pack[s] >> 25) & 7)) : 0.f;
            }
#pragma unroll
            for (int sl = 0; sl < NSLOT; sl++) {
                const float* wp =
                    w + ((size_t)(oc_base + wocS[sl]) * CTOT + ic0 + wiclS[sl]) * 9;
#pragma unroll
                for (int j = 0; j < 9; j++) pwv[sl][j] = __ldg(wp + j);
            }
        }

        const float4* swf4 = (const float4*)s_wf;
        const float2* sin2 = (const float2*)s_in;
#pragma unroll
        for (int kt = 0; kt < 9; kt++) {
            const int dy = kt / 3, dx = kt % 3;
            float4 af[NOM];
#pragma unroll
            for (int om = 0; om < NOM; om++)
                af[om] = swf4[om * 288 + kt * 32 + lane];
#pragma unroll
            for (int nt = 0; nt < 4; nt++) {
                int base = (pw + dy) * 34 + nt * 8 + g + dx;
                float2 b = sin2[t4 * 340 + base];
#pragma unroll
                for (int om = 0; om < NOM; om++)
                    mma8(C[om][nt], af[om].x, af[om].y, af[om].z, af[om].w, b.x, b.y);
            }
        }
        __syncthreads();
    }

    const int y = y0 + pw;
#pragma unroll
    for (int om = 0; om < NOM; om++) {
        const int o0 = oc_base + om * 16 + g, o1 = o0 + 8;
        const float bv0 = bias[o0], bv1 = bias[o1];
#pragma unroll
        for (int nt = 0; nt < 4; nt++) {
            int px = y * 32 + nt * 8 + 2 * t4;
            float r0 = fmaxf(C[om][nt][0] + bv0, 0.f);
            float r1 = fmaxf(C[om][nt][1] + bv0, 0.f);
            float r2 = fmaxf(C[om][nt][2] + bv1, 0.f);
            float r3 = fmaxf(C[om][nt][3] + bv1, 0.f);
            if (rnd) { r0 = f2tf(r0); r1 = f2tf(r1); r2 = f2tf(r2); r3 = f2tf(r3); }
            float2 v0 = {r0, r1}, v1 = {r2, r3};
            *(float2*)(out + (size_t)(bt * ld_out + o0) * 1024 + px) = v0;
            *(float2*)(out + (size_t)(bt * ld_out + o1) * 1024 + px) = v1;
        }
    }
}

// ---------------------------------------------------------------------------
// Fused Q/K/V projection: 128o x 128n per block, 3-stage cp.async pipeline.
// ---------------------------------------------------------------------------
__global__ __launch_bounds__(256) void proj_qkv_fused(float scaleQ)
{
    const int which = blockIdx.y;
    const float* X = which == 0 ? g_bev_feat : g_kv;
    const int Cdim = which == 0 ? 128 : 192;
    const int NCH = Cdim >> 3;
    const int NS = Cdim >> 4;
    const int wbase = which == 0 ? 0 : (which == 1 ? 16384 : 40960);

    const int n0 = blockIdx.x * 128;
    const int bt = blockIdx.z;
    const int tid = threadIdx.x;
    const int warp = tid >> 5, lane = tid & 31;
    const int g = lane >> 2, t4 = lane & 3;
    const int om2 = warp >> 1, nw = warp & 1;

    __shared__ __align__(16) float sX[3][16 * 132];
    __shared__ __align__(16) float sW[3][2048];

    float C[2][8][4];
#pragma unroll
    for (int mi = 0; mi < 2; mi++)
#pragma unroll
        for (int nt = 0; nt < 8; nt++)
#pragma unroll
            for (int i = 0; i < 4; i++) C[mi][nt][i] = 0.f;

    const float* xsrc = X + (size_t)bt * Cdim * 1024 + n0;
    const int r0 = tid >> 5, s0 = (tid & 31) * 4;
    const int r1 = (tid + 256) >> 5, s1 = ((tid + 256) & 31) * 4;
    int wdst[2];
    const float* wsrcc[2];
#pragma unroll
    for (int sl = 0; sl < 2; sl++) {
        int u = tid + sl * 256;
        int s = u >> 8, omAll = (u >> 5) & 7, ln = u & 31;
        wdst[sl] = u * 4;
        wsrcc[sl] = g_Wp + wbase + (omAll >= 4 ? NCH * 512 : 0) + s * 512 +
                    (omAll & 3) * 128 + ln * 4;
    }

#define QKV_STAGE(st, buf)                                                    \
    {                                                                         \
        CP16(&sX[buf][r0 * 132 + s0], xsrc + (size_t)((st) * 16 + r0) * 1024 + s0); \
        CP16(&sX[buf][r1 * 132 + s1], xsrc + (size_t)((st) * 16 + r1) * 1024 + s1); \
        CP16(&sW[buf][wdst[0]], wsrcc[0] + (st) * 1024);                      \
        CP16(&sW[buf][wdst[1]], wsrcc[1] + (st) * 1024);                      \
        CP_COMMIT();                                                          \
    }

    QKV_STAGE(0, 0);
    QKV_STAGE(1, 1);
    for (int st = 0; st < NS; st++) {
        const int buf = st % 3;
        if (st < NS - 1) CP_WAIT1(); else CP_WAIT0();
        __syncthreads();
        if (st + 2 < NS) QKV_STAGE(st + 2, (st + 2) % 3);
        const float4* sw4 = (const float4*)sW[buf];
#pragma unroll
        for (int s = 0; s < 2; s++) {
            float4 afA = sw4[s * 256 + om2 * 32 + lane];
            float4 afB = sw4[s * 256 + (om2 + 4) * 32 + lane];
#pragma unroll
            for (int nt = 0; nt < 8; nt++) {
                float b0 = sX[buf][(s * 8 + t4) * 132 + nw * 64 + nt * 8 + g];
                float b1 = sX[buf][(s * 8 + t4 + 4) * 132 + nw * 64 + nt * 8 + g];
                mma8(C[0][nt], afA.x, afA.y, afA.z, afA.w, b0, b1);
                mma8(C[1][nt], afB.x, afB.y, afB.z, afB.w, b0, b1);
            }
        }
    }
#undef QKV_STAGE

#pragma unroll
    for (int mi = 0; mi < 2; mi++) {
        const int omAll = om2 + mi * 4;
        const int o0 = omAll * 16 + g, o1 = o0 + 8;
        if (which == 0) {
            size_t b0 = (size_t)(bt * 4 + (o0 >> 5)) * 32768 + (o0 & 31);
            size_t b1 = (size_t)(bt * 4 + (o1 >> 5)) * 32768 + (o1 & 31);
#pragma unroll
            for (int nt = 0; nt < 8; nt++) {
                int n = n0 + nw * 64 + nt * 8 + 2 * t4;
                g_Q[b0 + (size_t)n * 32] = f2tf(C[mi][nt][0] * scaleQ);
                g_Q[b0 + (size_t)(n + 1) * 32] = f2tf(C[mi][nt][1] * scaleQ);
                g_Q[b1 + (size_t)n * 32] = f2tf(C[mi][nt][2] * scaleQ);
                g_Q[b1 + (size_t)(n + 1) * 32] = f2tf(C[mi][nt][3] * scaleQ);
            }
        } else {
            const int h = o0 >> 5;
            const int tile64 = blockIdx.x * 2 + nw;
            const int dh = omAll & 1;
            float* base = (which == 1 ? g_Kp : g_Vp) +
                          (size_t)((bt * 4 + h) * 16 + tile64) * 2048;
            if (which == 1) {
#pragma unroll
                for (int nt = 0; nt < 8; nt++) {
                    int foff = ((nt * 2 + dh) * 32 + 8 * t4 + (g & 3)) * 4 + (g >> 2);
                    base[foff]      = f2tf(C[mi][nt][0]);
                    base[foff + 16] = f2tf(C[mi][nt][1]);
                    base[foff + 2]  = f2tf(C[mi][nt][2]);
                    base[foff + 18] = f2tf(C[mi][nt][3]);
                }
            } else {
#pragma unroll
                for (int nt = 0; nt < 8; nt++) {
                    int foff = ((nt * 2 + dh) * 32 + g * 4 + t4) * 4;
                    float4 v = {f2tf(C[mi][nt][0]), f2tf(C[mi][nt][1]),
                                f2tf(C[mi][nt][2]), f2tf(C[mi][nt][3])};
                    *(float4*)(base + foff) = v;
                }
            }
        }
    }
}

// ---------------------------------------------------------------------------
// Output projection: 64o x 64n tiles (grid 256), 3-stage cp.async pipeline.
// ---------------------------------------------------------------------------
__global__ __launch_bounds__(256) void proj_out_mma(const float* __restrict__ bias)
{
    const int n0 = (blockIdx.x & 15) * 64;
    const int ogrp = blockIdx.x >> 4;
    const int o_base = ogrp * 64;
    const int bt = blockIdx.y;
    const int tid = threadIdx.x;
    const int warp = tid >> 5, lane = tid & 31;
    const int g = lane >> 2, t4 = lane & 3;
    const int om = warp >> 1, nw = warp & 1;

    __shared__ __align__(16) float sX[3][64 * 20];
    __shared__ __align__(16) float sW[3][1024];

    float C[4][4];
#pragma unroll
    for (int nt = 0; nt < 4; nt++)
#pragma unroll
        for (int i = 0; i < 4; i++) C[nt][i] = 0.f;

    const float* xsrc = g_attn + (size_t)(bt * 1024 + n0) * 128;
    const float* wsrc = g_Wp + 65536 + ogrp * 16 * 512;
    const int rn = tid >> 2, sg = (tid & 3) * 4;

#define OUT_STAGE(st, buf)                                                    \
    {                                                                         \
        CP16(&sX[buf][rn * 20 + sg], xsrc + (size_t)rn * 128 + (st) * 16 + sg); \
        CP16(&sW[buf][tid * 4], wsrc + (st) * 1024 + tid * 4);                \
        CP_COMMIT();                                                          \
    }

    OUT_STAGE(0, 0);
    OUT_STAGE(1, 1);
    for (int st = 0; st < 8; st++) {
        const int buf = st % 3;
        if (st < 7) CP_WAIT1(); else CP_WAIT0();
        __syncthreads();
        if (st + 2 < 8) OUT_STAGE(st + 2, (st + 2) % 3);
        const float4* sw4 = (const float4*)sW[buf];
#pragma unroll
        for (int s = 0; s < 2; s++) {
            float4 af = sw4[(s * 4 + om) * 32 + lane];
#pragma unroll
            for (int nt = 0; nt < 4; nt++) {
                int nn = nw * 32 + nt * 8 + g;
                float b0 = sX[buf][nn * 20 + s * 8 + t4];
                float b1 = sX[buf][nn * 20 + s * 8 + t4 + 4];
                mma8(C[nt], af.x, af.y, af.z, af.w, b0, b1);
            }
        }
    }
#undef OUT_STAGE

    const int o0 = o_base + om * 16 + g, o1 = o0 + 8;
    const float bv0 = bias[o0], bv1 = bias[o1];
#pragma unroll
    for (int nt = 0; nt < 4; nt++) {
        int n = n0 + nw * 32 + nt * 8 + 2 * t4;
        float2 v0 = {C[nt][0] + bv0, C[nt][1] + bv0};
        float2 v1 = {C[nt][2] + bv1, C[nt][3] + bv1};
        *(float2*)(g_fused + (size_t)(bt * 128 + o0) * 1024 + n) = v0;
        *(float2*)(g_fused + (size_t)(bt * 128 + o1) * 1024 + n) = v1;
    }
}

// ---------------------------------------------------------------------------
// Flash attention, 128q per block (unchanged from R13).
// ---------------------------------------------------------------------------
__global__ __launch_bounds__(128) void attn_mma_kernel() {
    const int q0 = blockIdx.x * 128;
    const int h = blockIdx.y;
    const int bt = blockIdx.z;
    const int tid = threadIdx.x;
    const int warp = tid >> 5, lane = tid & 31;
    const int g = lane >> 2, t4 = lane & 3;

    __shared__ __align__(16) float4 sK[2][512];
    __shared__ __align__(16) float4 sV[2][512];

    float qa[2][4][4];
#pragma unroll
    for (int qh = 0; qh < 2; qh++) {
        const float* qp =
            g_Q + ((size_t)(bt * 4 + h) * 1024 + q0 + warp * 32 + qh * 16) * 32;
#pragma unroll
        for (int dc = 0; dc < 4; dc++) {
            qa[qh][dc][0] = qp[g * 32 + dc * 8 + t4];
            qa[qh][dc][1] = qp[(g + 8) * 32 + dc * 8 + t4];
            qa[qh][dc][2] = qp[g * 32 + dc * 8 + t4 + 4];
            qa[qh][dc][3] = qp[(g + 8) * 32 + dc * 8 + t4 + 4];
        }
    }

    float O[2][4][4];
#pragma unroll
    for (int qh = 0; qh < 2; qh++)
#pragma unroll
        for (int dt = 0; dt < 4; dt++)
#pragma unroll
            for (int i = 0; i < 4; i++) O[qh][dt][i] = 0.f;
    float l[2][2] = {{0.f, 0.f}, {0.f, 0.f}};

    const float4* kg = (const float4*)(g_Kp + (size_t)(bt * 4 + h) * 16 * 2048);
    const float4* vg = (const float4*)(g_Vp + (size_t)(bt * 4 + h) * 16 * 2048);

#pragma unroll
    for (int j = 0; j < 4; j++) {
        CP16(&sK[0][j * 128 + tid], kg + j * 128 + tid);
        CP16(&sV[0][j * 128 + tid], vg + j * 128 + tid);
    }
    CP_COMMIT();

    for (int kt = 0; kt < 16; kt++) {
        const int cur = kt & 1;
        if (kt < 15) {
            const int nb = cur ^ 1;
            const float4* kn = kg + (kt + 1) * 512;
            const float4* vn = vg + (kt + 1) * 512;
#pragma unroll
            for (int j = 0; j < 4; j++) {
                CP16(&sK[nb][j * 128 + tid], kn + j * 128 + tid);
                CP16(&sV[nb][j * 128 + tid], vn + j * 128 + tid);
            }
            CP_COMMIT();
            CP_WAIT1();
        } else {
            CP_WAIT0();
        }
        __syncthreads();

        float S[2][8][4];
#pragma unroll
        for (int qh = 0; qh < 2; qh++)
#pragma unroll
            for (int nt = 0; nt < 8; nt++)
#pragma unroll
                for (int i = 0; i < 4; i++) S[qh][nt][i] = 0.f;

#pragma unroll
        for (int nt = 0; nt < 8; nt++) {
#pragma unroll
            for (int dch = 0; dch < 2; dch++) {
                float4 kf = sK[cur][(nt * 2 + dch) * 32 + lane];
#pragma unroll
                for (int qh = 0; qh < 2; qh++) {
                    mma8(S[qh][nt], qa[qh][2 * dch][0], qa[qh][2 * dch][1],
                         qa[qh][2 * dch][2], qa[qh][2 * dch][3], kf.x, kf.y);
                    mma8(S[qh][nt], qa[qh][2 * dch + 1][0], qa[qh][2 * dch + 1][1],
                         qa[qh][2 * dch + 1][2], qa[qh][2 * dch + 1][3], kf.z, kf.w);
                }
            }
        }

#pragma unroll
        for (int qh = 0; qh < 2; qh++)
#pragma unroll
            for (int nt = 0; nt < 8; nt++) {
                S[qh][nt][0] = ex2f(S[qh][nt][0]);
                S[qh][nt][1] = ex2f(S[qh][nt][1]);
                S[qh][nt][2] = ex2f(S[qh][nt][2]);
                S[qh][nt][3] = ex2f(S[qh][nt][3]);
                l[qh][0] += S[qh][nt][0] + S[qh][nt][1];
                l[qh][1] += S[qh][nt][2] + S[qh][nt][3];
                S[qh][nt][0] = f2tf(S[qh][nt][0]);
                S[qh][nt][1] = f2tf(S[qh][nt][1]);
                S[qh][nt][2] = f2tf(S[qh][nt][2]);
                S[qh][nt][3] = f2tf(S[qh][nt][3]);
            }

#pragma unroll
        for (int kc = 0; kc < 8; kc++) {
#pragma unroll
            for (int dth = 0; dth < 2; dth++) {
                float4 vf = sV[cur][(kc * 2 + dth) * 32 + lane];
#pragma unroll
                for (int qh = 0; qh < 2; qh++) {
                    float a0 = S[qh][kc][0], a1 = S[qh][kc][2];
                    float a2 = S[qh][kc][1], a3 = S[qh][kc][3];
                    mma8(O[qh][2 * dth], a0, a1, a2, a3, vf.x, vf.y);
                    mma8(O[qh][2 * dth + 1], a0, a1, a2, a3, vf.z, vf.w);
                }
            }
        }
        __syncthreads();
    }

#pragma unroll
    for (int qh = 0; qh < 2; qh++) {
        float l0 = l[qh][0], l1 = l[qh][1];
        l0 += __shfl_xor_sync(0xffffffff, l0, 1);
        l0 += __shfl_xor_sync(0xffffffff, l0, 2);
        l1 += __shfl_xor_sync(0xffffffff, l1, 1);
        l1 += __shfl_xor_sync(0xffffffff, l1, 2);
        float inv0 = 1.f / l0, inv1 = 1.f / l1;

        int q = q0 + warp * 32 + qh * 16 + g;
        size_t ob = (size_t)(bt * 1024 + q) * 128 + h * 32;
#pragma unroll
        for (int dt = 0; dt < 4; dt++) {
            float2 v0 = {O[qh][dt][0] * inv0, O[qh][dt][1] * inv0};
            float2 v1 = {O[qh][dt][2] * inv1, O[qh][dt][3] * inv1};
            *(float2*)(g_attn + ob + dt * 8 + 2 * t4) = v0;
            *(float2*)(g_attn + ob + 8 * 128 + dt * 8 + 2 * t4) = v1;
        }
    }
}

// ---------------------------------------------------------------------------
// Launch
// ---------------------------------------------------------------------------
extern "C" void kernel_launch(void* const* d_in, const int* in_sizes, int n_in,
                              void* d_out, int out_size) {
    const float* bev   = (const float*)d_in[0];
    const float* hd    = (const float*)d_in[1];
    const float* ego   = (const float*)d_in[2];
    const float* front = (const float*)d_in[3];
    const float* w_bev = (const float*)d_in[4];
    const float* b_bev = (const float*)d_in[5];
    const float* w_hd  = (const float*)d_in[6];
    const float* b_hd  = (const float*)d_in[7];
    const float* wq    = (const float*)d_in[8];
    const float* wk    = (const float*)d_in[9];
    const float* wv    = (const float*)d_in[10];
    const float* wo    = (const float*)d_in[11];
    const float* bo    = (const float*)d_in[12];
    const float* w_out = (const float*)d_in[13];
    const float* b_out = (const float*)d_in[14];
    float* out = (float*)d_out;

    float *p_bev_feat, *p_kv, *p_fused;
    cudaGetSymbolAddress((void**)&p_bev_feat, g_bev_feat);
    cudaGetSymbolAddress((void**)&p_kv, g_kv);
    cudaGetSymbolAddress((void**)&p_fused, g_fused);

    const float scaleQ = 0.17677669529663687f * 1.4426950408889634f;

    // 1. input convs (64oc x 8-row tiles) + resize + weight prep.
    conv_dual_kernel<64><<<dim3(40, 4, 8), 256>>>(
        bev, w_bev, b_bev, p_bev_feat, 128, 128, 144,
        hd, w_hd, b_hd, p_kv, 192, 64, 64,
        ego, 2, front, 4, wq, wk, wv, wo, 20, 1);

    // 2. Q/K/V projections (128o per block, 3-stage pipeline)
    proj_qkv_fused<<<dim3(8, 3, 8), 256>>>(scaleQ);

    // 3. attention (128q per block)
    attn_mma_kernel<<<dim3(8, 4, 8), 128>>>();

    // 4. output projection (64o x 64n, grid 256, 3-stage pipeline)
    proj_out_mma<<<dim3(32, 8), 256>>>(bo);

    // 5. final conv (32oc x 8-row; 128 blocks for wave packing)
    conv_dual_kernel<32><<<dim3(4, 4, 8), 256>>>(
        p_fused, w_out, b_out, out, 128, 128, 144,
        p_fused, w_out, b_out, out, 128, 128, 144,
        ego, 4, nullptr, 4, wq, wk, wv, wo, 4, 0);
}

// round 15
// speedup vs baseline: 1.0161x; 1.0161x over previous
#include <cuda_runtime.h>
#include <stdint.h>

// ---------------------------------------------------------------------------
// Scratch
// ---------------------------------------------------------------------------
__device__ float g_bev_feat[8 * 128 * 1024];   // (bt, c, n) tf32-rounded
__device__ float g_kv[8 * 192 * 1024];         // (bt, c, n) tf32-rounded
__device__ float g_Q[8 * 4 * 1024 * 32];       // (bt,h,n,d) tf32, scaled
__device__ float g_Kp[8 * 4 * 16 * 2048];      // packed B-fragments per 64-key tile
__device__ float g_Vp[8 * 4 * 16 * 2048];      // packed (incl. sigma permutation)
__device__ float g_attn[8 * 1024 * 128];       // (bt, n, c)
__device__ float g_fused[8 * 128 * 1024];      // (bt, c, n)
__device__ float g_Wp[81920];                  // fragment-packed tf32 wq|wk|wv|wo

// ---------------------------------------------------------------------------
// Helpers
// ---------------------------------------------------------------------------
__device__ __forceinline__ float f2tf(float x) {
    uint32_t u;
    asm("cvt.rna.tf32.f32 %0,%1;" : "=r"(u) : "f"(x));
    return __uint_as_float(u);
}
__device__ __forceinline__ float ex2f(float x) {
    float y;
    asm("ex2.approx.f32 %0,%1;" : "=f"(y) : "f"(x));
    return y;
}
__device__ __forceinline__ void mma8(float* c, float a0, float a1, float a2,
                                     float a3, float b0, float b1) {
    asm("mma.sync.aligned.m16n8k8.row.col.f32.tf32.tf32.f32 "
        "{%0,%1,%2,%3},{%4,%5,%6,%7},{%8,%9},{%0,%1,%2,%3};"
        : "+f"(c[0]), "+f"(c[1]), "+f"(c[2]), "+f"(c[3])
        : "r"(__float_as_uint(a0)), "r"(__float_as_uint(a1)),
          "r"(__float_as_uint(a2)), "r"(__float_as_uint(a3)),
          "r"(__float_as_uint(b0)), "r"(__float_as_uint(b1)));
}
#define CP16(dst, src)                                                        \
    {                                                                         \
        uint32_t _s = (uint32_t)__cvta_generic_to_shared(dst);                \
        asm volatile("cp.async.cg.shared.global [%0], [%1], 16;" ::"r"(_s),   \
                     "l"(src));                                               \
    }
#define CP_COMMIT() asm volatile("cp.async.commit_group;")
#define CP_WAIT0() asm volatile("cp.async.wait_group 0;")
#define CP_WAIT1() asm volatile("cp.async.wait_group 1;")

// ---------------------------------------------------------------------------
// Conv 3x3 SAME implicit GEMM, OCW oc x 256px (8 rows), dual-path.
// (unchanged from R13/R14)
// ---------------------------------------------------------------------------
template <int OCW>
__global__ __launch_bounds__(256) void conv_dual_kernel(
    const float* __restrict__ in0, const float* __restrict__ w0,
    const float* __restrict__ bias0, float* __restrict__ out0, int ld0, int cin0, int ctot0,
    const float* __restrict__ in1, const float* __restrict__ w1,
    const float* __restrict__ bias1, float* __restrict__ out1, int ld1, int cin1, int ctot1,
    const float* __restrict__ ego, int xsplit,
    const float* __restrict__ front, int rsplit,
    const float* __restrict__ wq, const float* __restrict__ wk,
    const float* __restrict__ wv, const float* __restrict__ wo,
    int psplit, int rnd)
{
    constexpr int NOM = OCW / 16;
    constexpr int NSLOT = OCW / 32;

    if ((int)blockIdx.x >= psplit) {
        if (blockIdx.z != 0) return;
        int t = ((blockIdx.x - psplit) * 4 + blockIdx.y) * 256 + threadIdx.x;
        if (t >= 20480) return;
        int which, rem, Cdim, base;
        if (t < 4096)       { which = 0; rem = t;         Cdim = 128; base = 0; }
        else if (t < 10240) { which = 1; rem = t - 4096;  Cdim = 192; base = 16384; }
        else if (t < 16384) { which = 2; rem = t - 10240; Cdim = 192; base = 40960; }
        else                { which = 3; rem = t - 16384; Cdim = 128; base = 65536; }
        const float* W = which == 0 ? wq : (which == 1 ? wk : (which == 2 ? wv : wo));
        int NCH = Cdim >> 3;
        int lane = rem & 31;
        int om = (rem >> 5) & 3;
        int sg = (rem >> 7) % NCH;
        int ogrp = (rem >> 7) / NCH;
        int g2 = lane >> 2, t4 = lane & 3;
        int o = ogrp * 64 + om * 16 + g2;
        int k = sg * 8 + t4;
        float4 v;
        v.x = f2tf(W[(size_t)o * Cdim + k]);
        v.y = f2tf(W[(size_t)(o + 8) * Cdim + k]);
        v.z = f2tf(W[(size_t)o * Cdim + k + 4]);
        v.w = f2tf(W[(size_t)(o + 8) * Cdim + k + 4]);
        *(float4*)&g_Wp[base + rem * 4] = v;
        return;
    }

    if ((int)blockIdx.x >= rsplit) {
        int idx = ((blockIdx.x - rsplit) * 4 + blockIdx.y) * 256 + threadIdx.x;
        int bt = blockIdx.z;
        int c = idx >> 8, p4 = (idx & 255) * 4;
        int y = p4 >> 5;
        const float* src = front + (bt * 64 + c) * 256;
        float sy = y * 0.5f - 0.25f;
        int y0 = __float2int_rd(sy);
        float fy = sy - (float)y0;
        int y0c = max(y0, 0), y1c = min(y0 + 1, 15);
        float o[4];
#pragma unroll
        for (int i = 0; i < 4; i++) {
            int x = (p4 & 31) + i;
            float sx = x * 0.5f - 0.25f;
            int x0 = __float2int_rd(sx);
            float fx = sx - (float)x0;
            int x0c = max(x0, 0), x1c = min(x0 + 1, 15);
            float a = src[y0c * 16 + x0c], b = src[y0c * 16 + x1c];
            float cc = src[y1c * 16 + x0c], d = src[y1c * 16 + x1c];
            float top = a + fx * (b - a), bot = cc + fx * (d - cc);
            o[i] = f2tf(top + fy * (bot - top));
        }
        float4 v = {o[0], o[1], o[2], o[3]};
        *(float4*)(g_kv + (size_t)(bt * 192 + 128 + c) * 1024 + p4) = v;
        return;
    }

    const int path = (int)blockIdx.x >= xsplit;
    const float* in = path ? in1 : in0;
    const float* w = path ? w1 : w0;
    const float* bias = path ? bias1 : bias0;
    float* out = path ? out1 : out0;
    const int ld_out = path ? ld1 : ld0;
    const int CIN = path ? cin1 : cin0;
    const int CTOT = path ? ctot1 : ctot0;
    const int NCH = CTOT >> 3;
    const int oc_base = (path ? blockIdx.x - xsplit : blockIdx.x) * OCW;
    const int y0 = blockIdx.y * 8;
    const int bt = blockIdx.z;
    const int tid = threadIdx.x;
    const int warp = tid >> 5, lane = tid & 31;
    const int g = lane >> 2, t4 = lane & 3;
    const int pw = warp;

    __shared__ float s_in[4 * 680];
    __shared__ float s_wf[NOM * 1152];

    int pack[11];
    unsigned vmask = 0, amask = 0;
#pragma unroll
    for (int s = 0; s < 11; s++) {
        int idx = tid + s * 256;
        pack[s] = 0;
        if (idx < 2720) {
            amask |= 1u << s;
            int icl = idx / 340, rem = idx - icl * 340;
            int rr = rem / 34, cc = rem - rr * 34;
            int Y = y0 - 1 + rr, X = cc - 1;
            int sdst = (icl & 3) * 680 + rem * 2 + (icl >> 2);
            int ssrc = 0;
            if ((unsigned)Y < 32u && (unsigned)X < 32u) {
                vmask |= 1u << s;
                ssrc = icl * 1024 + Y * 32 + X;
            }
            pack[s] = sdst | (ssrc << 12) | (icl << 25);
        }
    }
    int wocS[NSLOT], wiclS[NSLOT], wfbS[NSLOT];
#pragma unroll
    for (int sl = 0; sl < NSLOT; sl++) {
        int s = tid + sl * 256;
        int woc = s >> 3, wicl = s & 7;
        wocS[sl] = woc; wiclS[sl] = wicl;
        wfbS[sl] = (woc >> 4) * 1152 + ((woc & 7) * 4 + (wicl & 3)) * 4 +
                   ((woc >> 3) & 1) + 2 * (wicl >> 2);
    }

    float C[NOM][4][4];
#pragma unroll
    for (int om = 0; om < NOM; om++)
#pragma unroll
        for (int nt = 0; nt < 4; nt++)
#pragma unroll
            for (int i = 0; i < 4; i++) C[om][nt][i] = 0.f;

    float pin[11], pwv[NSLOT][9];
    {
        const float* src = in + (size_t)bt * CIN * 1024;
#pragma unroll
        for (int s = 0; s < 11; s++)
            pin[s] = (vmask >> s & 1) ? __ldg(src + ((pack[s] >> 12) & 0x1FFF)) : 0.f;
#pragma unroll
        for (int sl = 0; sl < NSLOT; sl++) {
            const float* wp = w + ((size_t)(oc_base + wocS[sl]) * CTOT + wiclS[sl]) * 9;
#pragma unroll
            for (int j = 0; j < 9; j++) pwv[sl][j] = __ldg(wp + j);
        }
    }

    for (int ch = 0; ch < NCH; ch++) {
#pragma unroll
        for (int s = 0; s < 11; s++)
            if (amask >> s & 1) s_in[pack[s] & 0xFFF] = f2tf(pin[s]);
#pragma unroll
        for (int sl = 0; sl < NSLOT; sl++)
#pragma unroll
            for (int j = 0; j < 9; j++) s_wf[wfbS[sl] + j * 128] = f2tf(pwv[sl][j]);
        __syncthreads();

        if (ch + 1 < NCH) {
            int ic0 = (ch + 1) * 8;
            if (ic0 < CIN) {
                const float* src = in + (size_t)(bt * CIN + ic0) * 1024;
#pragma unroll
                for (int s = 0; s < 11; s++)
                    pin[s] = (vmask >> s & 1) ? __ldg(src + ((pack[s] >> 12) & 0x1FFF)) : 0.f;
            } else {
                const float* e = ego + bt * 16 + (ic0 - CIN);
#pragma unroll
                for (int s = 0; s < 11; s++)
                    pin[s] = (vmask >> s & 1) ? __ldg(e + ((pack[s] >> 25) & 7)) : 0.f;
            }
#pragma unroll
            for (int sl = 0; sl < NSLOT; sl++) {
                const float* wp =
                    w + ((size_t)(oc_base + wocS[sl]) * CTOT + ic0 + wiclS[sl]) * 9;
#pragma unroll
                for (int j = 0; j < 9; j++) pwv[sl][j] = __ldg(wp + j);
            }
        }

        const float4* swf4 = (const float4*)s_wf;
        const float2* sin2 = (const float2*)s_in;
#pragma unroll
        for (int kt = 0; kt < 9; kt++) {
            const int dy = kt / 3, dx = kt % 3;
            float4 af[NOM];
#pragma unroll
            for (int om = 0; om < NOM; om++)
                af[om] = swf4[om * 288 + kt * 32 + lane];
#pragma unroll
            for (int nt = 0; nt < 4; nt++) {
                int base = (pw + dy) * 34 + nt * 8 + g + dx;
                float2 b = sin2[t4 * 340 + base];
#pragma unroll
                for (int om = 0; om < NOM; om++)
                    mma8(C[om][nt], af[om].x, af[om].y, af[om].z, af[om].w, b.x, b.y);
            }
        }
        __syncthreads();
    }

    const int y = y0 + pw;
#pragma unroll
    for (int om = 0; om < NOM; om++) {
        const int o0 = oc_base + om * 16 + g, o1 = o0 + 8;
        const float bv0 = bias[o0], bv1 = bias[o1];
#pragma unroll
        for (int nt = 0; nt < 4; nt++) {
            int px = y * 32 + nt * 8 + 2 * t4;
            float r0 = fmaxf(C[om][nt][0] + bv0, 0.f);
            float r1 = fmaxf(C[om][nt][1] + bv0, 0.f);
            float r2 = fmaxf(C[om][nt][2] + bv1, 0.f);
            float r3 = fmaxf(C[om][nt][3] + bv1, 0.f);
            if (rnd) { r0 = f2tf(r0); r1 = f2tf(r1); r2 = f2tf(r2); r3 = f2tf(r3); }
            float2 v0 = {r0, r1}, v1 = {r2, r3};
            *(float2*)(out + (size_t)(bt * ld_out + o0) * 1024 + px) = v0;
            *(float2*)(out + (size_t)(bt * ld_out + o1) * 1024 + px) = v1;
        }
    }
}

// ---------------------------------------------------------------------------
// Fused Q/K/V projection: 128o x 128n per block, 3-stage cp.async pipeline.
// (unchanged from R14)
// ---------------------------------------------------------------------------
__global__ __launch_bounds__(256) void proj_qkv_fused(float scaleQ)
{
    const int which = blockIdx.y;
    const float* X = which == 0 ? g_bev_feat : g_kv;
    const int Cdim = which == 0 ? 128 : 192;
    const int NCH = Cdim >> 3;
    const int NS = Cdim >> 4;
    const int wbase = which == 0 ? 0 : (which == 1 ? 16384 : 40960);

    const int n0 = blockIdx.x * 128;
    const int bt = blockIdx.z;
    const int tid = threadIdx.x;
    const int warp = tid >> 5, lane = tid & 31;
    const int g = lane >> 2, t4 = lane & 3;
    const int om2 = warp >> 1, nw = warp & 1;

    __shared__ __align__(16) float sX[3][16 * 132];
    __shared__ __align__(16) float sW[3][2048];

    float C[2][8][4];
#pragma unroll
    for (int mi = 0; mi < 2; mi++)
#pragma unroll
        for (int nt = 0; nt < 8; nt++)
#pragma unroll
            for (int i = 0; i < 4; i++) C[mi][nt][i] = 0.f;

    const float* xsrc = X + (size_t)bt * Cdim * 1024 + n0;
    const int r0 = tid >> 5, s0 = (tid & 31) * 4;
    const int r1 = (tid + 256) >> 5, s1 = ((tid + 256) & 31) * 4;
    int wdst[2];
    const float* wsrcc[2];
#pragma unroll
    for (int sl = 0; sl < 2; sl++) {
        int u = tid + sl * 256;
        int s = u >> 8, omAll = (u >> 5) & 7, ln = u & 31;
        wdst[sl] = u * 4;
        wsrcc[sl] = g_Wp + wbase + (omAll >= 4 ? NCH * 512 : 0) + s * 512 +
                    (omAll & 3) * 128 + ln * 4;
    }

#define QKV_STAGE(st, buf)                                                    \
    {                                                                         \
        CP16(&sX[buf][r0 * 132 + s0], xsrc + (size_t)((st) * 16 + r0) * 1024 + s0); \
        CP16(&sX[buf][r1 * 132 + s1], xsrc + (size_t)((st) * 16 + r1) * 1024 + s1); \
        CP16(&sW[buf][wdst[0]], wsrcc[0] + (st) * 1024);                      \
        CP16(&sW[buf][wdst[1]], wsrcc[1] + (st) * 1024);                      \
        CP_COMMIT();                                                          \
    }

    QKV_STAGE(0, 0);
    QKV_STAGE(1, 1);
    for (int st = 0; st < NS; st++) {
        const int buf = st % 3;
        if (st < NS - 1) CP_WAIT1(); else CP_WAIT0();
        __syncthreads();
        if (st + 2 < NS) QKV_STAGE(st + 2, (st + 2) % 3);
        const float4* sw4 = (const float4*)sW[buf];
#pragma unroll
        for (int s = 0; s < 2; s++) {
            float4 afA = sw4[s * 256 + om2 * 32 + lane];
            float4 afB = sw4[s * 256 + (om2 + 4) * 32 + lane];
#pragma unroll
            for (int nt = 0; nt < 8; nt++) {
                float b0 = sX[buf][(s * 8 + t4) * 132 + nw * 64 + nt * 8 + g];
                float b1 = sX[buf][(s * 8 + t4 + 4) * 132 + nw * 64 + nt * 8 + g];
                mma8(C[0][nt], afA.x, afA.y, afA.z, afA.w, b0, b1);
                mma8(C[1][nt], afB.x, afB.y, afB.z, afB.w, b0, b1);
            }
        }
    }
#undef QKV_STAGE

#pragma unroll
    for (int mi = 0; mi < 2; mi++) {
        const int omAll = om2 + mi * 4;
        const int o0 = omAll * 16 + g, o1 = o0 + 8;
        if (which == 0) {
            size_t b0 = (size_t)(bt * 4 + (o0 >> 5)) * 32768 + (o0 & 31);
            size_t b1 = (size_t)(bt * 4 + (o1 >> 5)) * 32768 + (o1 & 31);
#pragma unroll
            for (int nt = 0; nt < 8; nt++) {
                int n = n0 + nw * 64 + nt * 8 + 2 * t4;
                g_Q[b0 + (size_t)n * 32] = f2tf(C[mi][nt][0] * scaleQ);
                g_Q[b0 + (size_t)(n + 1) * 32] = f2tf(C[mi][nt][1] * scaleQ);
                g_Q[b1 + (size_t)n * 32] = f2tf(C[mi][nt][2] * scaleQ);
                g_Q[b1 + (size_t)(n + 1) * 32] = f2tf(C[mi][nt][3] * scaleQ);
            }
        } else {
            const int h = o0 >> 5;
            const int tile64 = blockIdx.x * 2 + nw;
            const int dh = omAll & 1;
            float* base = (which == 1 ? g_Kp : g_Vp) +
                          (size_t)((bt * 4 + h) * 16 + tile64) * 2048;
            if (which == 1) {
#pragma unroll
                for (int nt = 0; nt < 8; nt++) {
                    int foff = ((nt * 2 + dh) * 32 + 8 * t4 + (g & 3)) * 4 + (g >> 2);
                    base[foff]      = f2tf(C[mi][nt][0]);
                    base[foff + 16] = f2tf(C[mi][nt][1]);
                    base[foff + 2]  = f2tf(C[mi][nt][2]);
                    base[foff + 18] = f2tf(C[mi][nt][3]);
                }
            } else {
#pragma unroll
                for (int nt = 0; nt < 8; nt++) {
                    int foff = ((nt * 2 + dh) * 32 + g * 4 + t4) * 4;
                    float4 v = {f2tf(C[mi][nt][0]), f2tf(C[mi][nt][1]),
                                f2tf(C[mi][nt][2]), f2tf(C[mi][nt][3])};
                    *(float4*)(base + foff) = v;
                }
            }
        }
    }
}

// ---------------------------------------------------------------------------
// Output projection: 64o x 64n tiles (grid 256), 3-stage pipeline (R14).
// ---------------------------------------------------------------------------
__global__ __launch_bounds__(256) void proj_out_mma(const float* __restrict__ bias)
{
    const int n0 = (blockIdx.x & 15) * 64;
    const int ogrp = blockIdx.x >> 4;
    const int o_base = ogrp * 64;
    const int bt = blockIdx.y;
    const int tid = threadIdx.x;
    const int warp = tid >> 5, lane = tid & 31;
    const int g = lane >> 2, t4 = lane & 3;
    const int om = warp >> 1, nw = warp & 1;

    __shared__ __align__(16) float sX[3][64 * 20];
    __shared__ __align__(16) float sW[3][1024];

    float C[4][4];
#pragma unroll
    for (int nt = 0; nt < 4; nt++)
#pragma unroll
        for (int i = 0; i < 4; i++) C[nt][i] = 0.f;

    const float* xsrc = g_attn + (size_t)(bt * 1024 + n0) * 128;
    const float* wsrc = g_Wp + 65536 + ogrp * 16 * 512;
    const int rn = tid >> 2, sg = (tid & 3) * 4;

#define OUT_STAGE(st, buf)                                                    \
    {                                                                         \
        CP16(&sX[buf][rn * 20 + sg], xsrc + (size_t)rn * 128 + (st) * 16 + sg); \
        CP16(&sW[buf][tid * 4], wsrc + (st) * 1024 + tid * 4);                \
        CP_COMMIT();                                                          \
    }

    OUT_STAGE(0, 0);
    OUT_STAGE(1, 1);
    for (int st = 0; st < 8; st++) {
        const int buf = st % 3;
        if (st < 7) CP_WAIT1(); else CP_WAIT0();
        __syncthreads();
        if (st + 2 < 8) OUT_STAGE(st + 2, (st + 2) % 3);
        const float4* sw4 = (const float4*)sW[buf];
#pragma unroll
        for (int s = 0; s < 2; s++) {
            float4 af = sw4[(s * 4 + om) * 32 + lane];
#pragma unroll
            for (int nt = 0; nt < 4; nt++) {
                int nn = nw * 32 + nt * 8 + g;
                float b0 = sX[buf][nn * 20 + s * 8 + t4];
                float b1 = sX[buf][nn * 20 + s * 8 + t4 + 4];
                mma8(C[nt], af.x, af.y, af.z, af.w, b0, b1);
            }
        }
    }
#undef OUT_STAGE

    const int o0 = o_base + om * 16 + g, o1 = o0 + 8;
    const float bv0 = bias[o0], bv1 = bias[o1];
#pragma unroll
    for (int nt = 0; nt < 4; nt++) {
        int n = n0 + nw * 32 + nt * 8 + 2 * t4;
        float2 v0 = {C[nt][0] + bv0, C[nt][1] + bv0};
        float2 v1 = {C[nt][2] + bv1, C[nt][3] + bv1};
        *(float2*)(g_fused + (size_t)(bt * 128 + o0) * 1024 + n) = v0;
        *(float2*)(g_fused + (size_t)(bt * 128 + o1) * 1024 + n) = v1;
    }
}

// ---------------------------------------------------------------------------
// Flash attention, 128q per block, 128-key tiles (two 64-key halves per
// barrier round): 8 sync/wait rounds instead of 16. grid (8, 4, 8), block 128.
// ---------------------------------------------------------------------------
__global__ __launch_bounds__(128) void attn_mma_kernel() {
    const int q0 = blockIdx.x * 128;
    const int h = blockIdx.y;
    const int bt = blockIdx.z;
    const int tid = threadIdx.x;
    const int warp = tid >> 5, lane = tid & 31;
    const int g = lane >> 2, t4 = lane & 3;

    __shared__ __align__(16) float4 sK[2][1024];
    __shared__ __align__(16) float4 sV[2][1024];

    float qa[2][4][4];
#pragma unroll
    for (int qh = 0; qh < 2; qh++) {
        const float* qp =
            g_Q + ((size_t)(bt * 4 + h) * 1024 + q0 + warp * 32 + qh * 16) * 32;
#pragma unroll
        for (int dc = 0; dc < 4; dc++) {
            qa[qh][dc][0] = qp[g * 32 + dc * 8 + t4];
            qa[qh][dc][1] = qp[(g + 8) * 32 + dc * 8 + t4];
            qa[qh][dc][2] = qp[g * 32 + dc * 8 + t4 + 4];
            qa[qh][dc][3] = qp[(g + 8) * 32 + dc * 8 + t4 + 4];
        }
    }

    float O[2][4][4];
#pragma unroll
    for (int qh = 0; qh < 2; qh++)
#pragma unroll
        for (int dt = 0; dt < 4; dt++)
#pragma unroll
            for (int i = 0; i < 4; i++) O[qh][dt][i] = 0.f;
    float l[2][2] = {{0.f, 0.f}, {0.f, 0.f}};

    const float4* kg = (const float4*)(g_Kp + (size_t)(bt * 4 + h) * 16 * 2048);
    const float4* vg = (const float4*)(g_Vp + (size_t)(bt * 4 + h) * 16 * 2048);

#pragma unroll
    for (int j = 0; j < 8; j++) {
        CP16(&sK[0][j * 128 + tid], kg + j * 128 + tid);
        CP16(&sV[0][j * 128 + tid], vg + j * 128 + tid);
    }
    CP_COMMIT();

    for (int kt = 0; kt < 8; kt++) {
        const int cur = kt & 1;
        if (kt < 7) {
            const int nb = cur ^ 1;
            const float4* kn = kg + (kt + 1) * 1024;
            const float4* vn = vg + (kt + 1) * 1024;
#pragma unroll
            for (int j = 0; j < 8; j++) {
                CP16(&sK[nb][j * 128 + tid], kn + j * 128 + tid);
                CP16(&sV[nb][j * 128 + tid], vn + j * 128 + tid);
            }
            CP_COMMIT();
            CP_WAIT1();
        } else {
            CP_WAIT0();
        }
        __syncthreads();

#pragma unroll
        for (int h2 = 0; h2 < 2; h2++) {
            const int hb2 = h2 * 512;
            float S[2][8][4];
#pragma unroll
            for (int qh = 0; qh < 2; qh++)
#pragma unroll
                for (int nt = 0; nt < 8; nt++)
#pragma unroll
                    for (int i = 0; i < 4; i++) S[qh][nt][i] = 0.f;

#pragma unroll
            for (int nt = 0; nt < 8; nt++) {
#pragma unroll
                for (int dch = 0; dch < 2; dch++) {
                    float4 kf = sK[cur][hb2 + (nt * 2 + dch) * 32 + lane];
#pragma unroll
                    for (int qh = 0; qh < 2; qh++) {
                        mma8(S[qh][nt], qa[qh][2 * dch][0], qa[qh][2 * dch][1],
                             qa[qh][2 * dch][2], qa[qh][2 * dch][3], kf.x, kf.y);
                        mma8(S[qh][nt], qa[qh][2 * dch + 1][0],
                             qa[qh][2 * dch + 1][1], qa[qh][2 * dch + 1][2],
                             qa[qh][2 * dch + 1][3], kf.z, kf.w);
                    }
                }
            }

#pragma unroll
            for (int qh = 0; qh < 2; qh++)
#pragma unroll
                for (int nt = 0; nt < 8; nt++) {
                    S[qh][nt][0] = ex2f(S[qh][nt][0]);
                    S[qh][nt][1] = ex2f(S[qh][nt][1]);
                    S[qh][nt][2] = ex2f(S[qh][nt][2]);
                    S[qh][nt][3] = ex2f(S[qh][nt][3]);
                    l[qh][0] += S[qh][nt][0] + S[qh][nt][1];
                    l[qh][1] += S[qh][nt][2] + S[qh][nt][3];
                    S[qh][nt][0] = f2tf(S[qh][nt][0]);
                    S[qh][nt][1] = f2tf(S[qh][nt][1]);
                    S[qh][nt][2] = f2tf(S[qh][nt][2]);
                    S[qh][nt][3] = f2tf(S[qh][nt][3]);
                }

#pragma unroll
            for (int kc = 0; kc < 8; kc++) {
#pragma unroll
                for (int dth = 0; dth < 2; dth++) {
                    float4 vf = sV[cur][hb2 + (kc * 2 + dth) * 32 + lane];
#pragma unroll
                    for (int qh = 0; qh < 2; qh++) {
                        float a0 = S[qh][kc][0], a1 = S[qh][kc][2];
                        float a2 = S[qh][kc][1], a3 = S[qh][kc][3];
                        mma8(O[qh][2 * dth], a0, a1, a2, a3, vf.x, vf.y);
                        mma8(O[qh][2 * dth + 1], a0, a1, a2, a3, vf.z, vf.w);
                    }
                }
            }
        }
        __syncthreads();
    }

#pragma unroll
    for (int qh = 0; qh < 2; qh++) {
        float l0 = l[qh][0], l1 = l[qh][1];
        l0 += __shfl_xor_sync(0xffffffff, l0, 1);
        l0 += __shfl_xor_sync(0xffffffff, l0, 2);
        l1 += __shfl_xor_sync(0xffffffff, l1, 1);
        l1 += __shfl_xor_sync(0xffffffff, l1, 2);
        float inv0 = 1.f / l0, inv1 = 1.f / l1;

        int q = q0 + warp * 32 + qh * 16 + g;
        size_t ob = (size_t)(bt * 1024 + q) * 128 + h * 32;
#pragma unroll
        for (int dt = 0; dt < 4; dt++) {
            float2 v0 = {O[qh][dt][0] * inv0, O[qh][dt][1] * inv0};
            float2 v1 = {O[qh][dt][2] * inv1, O[qh][dt][3] * inv1};
            *(float2*)(g_attn + ob + dt * 8 + 2 * t4) = v0;
            *(float2*)(g_attn + ob + 8 * 128 + dt * 8 + 2 * t4) = v1;
        }
    }
}

// ---------------------------------------------------------------------------
// Launch
// ---------------------------------------------------------------------------
extern "C" void kernel_launch(void* const* d_in, const int* in_sizes, int n_in,
                              void* d_out, int out_size) {
    const float* bev   = (const float*)d_in[0];
    const float* hd    = (const float*)d_in[1];
    const float* ego   = (const float*)d_in[2];
    const float* front = (const float*)d_in[3];
    const float* w_bev = (const float*)d_in[4];
    const float* b_bev = (const float*)d_in[5];
    const float* w_hd  = (const float*)d_in[6];
    const float* b_hd  = (const float*)d_in[7];
    const float* wq    = (const float*)d_in[8];
    const float* wk    = (const float*)d_in[9];
    const float* wv    = (const float*)d_in[10];
    const float* wo    = (const float*)d_in[11];
    const float* bo    = (const float*)d_in[12];
    const float* w_out = (const float*)d_in[13];
    const float* b_out = (const float*)d_in[14];
    float* out = (float*)d_out;

    float *p_bev_feat, *p_kv, *p_fused;
    cudaGetSymbolAddress((void**)&p_bev_feat, g_bev_feat);
    cudaGetSymbolAddress((void**)&p_kv, g_kv);
    cudaGetSymbolAddress((void**)&p_fused, g_fused);

    const float scaleQ = 0.17677669529663687f * 1.4426950408889634f;

    // 1. input convs (64oc x 8-row tiles) + resize + weight prep.
    conv_dual_kernel<64><<<dim3(40, 4, 8), 256>>>(
        bev, w_bev, b_bev, p_bev_feat, 128, 128, 144,
        hd, w_hd, b_hd, p_kv, 192, 64, 64,
        ego, 2, front, 4, wq, wk, wv, wo, 20, 1);

    // 2. Q/K/V projections (128o per block, 3-stage pipeline)
    proj_qkv_fused<<<dim3(8, 3, 8), 256>>>(scaleQ);

    // 3. attention (128q per block, 128-key tiles)
    attn_mma_kernel<<<dim3(8, 4, 8), 128>>>();

    // 4. output projection (64o x 64n, grid 256, 3-stage pipeline)
    proj_out_mma<<<dim3(32, 8), 256>>>(bo);

    // 5. final conv (32oc x 8-row; 128 blocks for wave packing)
    conv_dual_kernel<32><<<dim3(4, 4, 8), 256>>>(
        p_fused, w_out, b_out, out, 128, 128, 144,
        p_fused, w_out, b_out, out, 128, 128, 144,
        ego, 4, nullptr, 4, wq, wk, wv, wo, 4, 0);
}